// round 6
// baseline (speedup 1.0000x reference)
#include <cuda_runtime.h>
#include <cuda_bf16.h>
#include <cuda_fp8.h>
#include <cstdint>
#include <math.h>

// ---------------------------------------------------------------------------
// Problem dims
// ---------------------------------------------------------------------------
#define BB 4
#define SS 4096
#define DD 2048
#define EE 2048
#define MM (BB*SS)         // 16384
#define NCHUNK 64
#define LCHUNK (SS/NCHUNK) // 64

// GEMM tiling: CTA 128x128, BK=64, warps 4(m) x 2(n), warp tile 32x64
#define Bb_M 128
#define Bb_N 128
#define Bb_K 64
#define KSTAGES (DD/Bb_K)  // 32

// Stage smem (bytes): 4 tiles of 128 rows x 128B
#define AHI_OFF 0
#define ACR_OFF 16384
#define BHI_OFF 32768
#define BCR_OFF 49152
#define STAGE_BYTES 65536
#define NSTAGE 3
#define SMEM_TOTAL (NSTAGE*STAGE_BYTES)   // 196608

// fp8 correction scales
#define S_LO_X 4096.0f      // 2^12
#define S_HI_W 32.0f        // 2^5
#define S_LO_W 131072.0f    // 2^17
#define S_INV  (1.0f/131072.0f)

// ---------------------------------------------------------------------------
// Device scratch
// ---------------------------------------------------------------------------
__device__ __nv_bfloat16 g_xhi[(size_t)MM * DD];          // 64 MB bf16 hi(x)
__device__ uint8_t       g_xc8[(size_t)MM * DD * 2];      // 64 MB fp8 [lo|hi] interleave
__device__ __nv_bfloat16 g_whi[(size_t)4 * DD * EE];      // 32 MB bf16 hi(W) q,k,v,g
__device__ uint8_t       g_wc8[(size_t)4 * DD * EE * 2];  // 32 MB fp8 [hi|lo] interleave
__device__ float g_q[(size_t)MM * EE];
__device__ float g_k[(size_t)MM * EE];
__device__ float g_v[(size_t)MM * EE];
__device__ float g_g[(size_t)MM * EE];
__device__ float g_sums[(size_t)BB * EE * NCHUNK];

// ---------------------------------------------------------------------------
// Helpers
// ---------------------------------------------------------------------------
__device__ __forceinline__ uint32_t smem_u32(const void* p) {
    uint32_t a;
    asm("{ .reg .u64 t; cvta.to.shared.u64 t, %1; cvt.u32.u64 %0, t; }"
        : "=r"(a) : "l"(p));
    return a;
}
__device__ __forceinline__ void cp_async16(uint32_t dst, const void* src) {
    asm volatile("cp.async.cg.shared.global [%0], [%1], 16;"
                 :: "r"(dst), "l"(src) : "memory");
}
#define CP_COMMIT() asm volatile("cp.async.commit_group;" ::: "memory")
#define CP_WAIT1()  asm volatile("cp.async.wait_group 1;" ::: "memory")
#define CP_WAIT0()  asm volatile("cp.async.wait_group 0;" ::: "memory")

__device__ __forceinline__ void ldsm4(uint32_t (&r)[4], uint32_t addr) {
    asm volatile("ldmatrix.sync.aligned.m8n8.x4.shared.b16 {%0,%1,%2,%3}, [%4];"
                 : "=r"(r[0]), "=r"(r[1]), "=r"(r[2]), "=r"(r[3]) : "r"(addr));
}
__device__ __forceinline__ void mma16816(float (&c)[4], const uint32_t (&a)[4],
                                         uint32_t b0, uint32_t b1) {
    asm volatile("mma.sync.aligned.m16n8k16.row.col.f32.bf16.bf16.f32 "
                 "{%0,%1,%2,%3}, {%4,%5,%6,%7}, {%8,%9}, {%0,%1,%2,%3};"
                 : "+f"(c[0]), "+f"(c[1]), "+f"(c[2]), "+f"(c[3])
                 : "r"(a[0]), "r"(a[1]), "r"(a[2]), "r"(a[3]), "r"(b0), "r"(b1));
}
__device__ __forceinline__ void mma16832f8(float (&c)[4], const uint32_t (&a)[4],
                                           uint32_t b0, uint32_t b1) {
    asm volatile("mma.sync.aligned.m16n8k32.row.col.f32.e4m3.e4m3.f32 "
                 "{%0,%1,%2,%3}, {%4,%5,%6,%7}, {%8,%9}, {%0,%1,%2,%3};"
                 : "+f"(c[0]), "+f"(c[1]), "+f"(c[2]), "+f"(c[3])
                 : "r"(a[0]), "r"(a[1]), "r"(a[2]), "r"(a[3]), "r"(b0), "r"(b1));
}
// SW128 swizzled byte offset inside a [row][128B] tile
__device__ __forceinline__ uint32_t swz(uint32_t row, uint32_t ch) {
    return row * 128u + (((ch ^ (row & 7u)) & 7u) << 4);
}
__device__ __forceinline__ uint32_t pack4_e4m3(float a, float b, float c, float d) {
    __nv_fp8x2_storage_t p0 = __nv_cvt_float2_to_fp8x2(make_float2(a, b),
                                                       __NV_SATFINITE, __NV_E4M3);
    __nv_fp8x2_storage_t p1 = __nv_cvt_float2_to_fp8x2(make_float2(c, d),
                                                       __NV_SATFINITE, __NV_E4M3);
    return (uint32_t)p0 | ((uint32_t)p1 << 16);
}

// ---------------------------------------------------------------------------
// Prepack x: per thread one (m, 16k block): bf16 hi + fp8 [4096*lo | hi]
// ---------------------------------------------------------------------------
__global__ __launch_bounds__(256) void conv_x_kernel(const float* __restrict__ x)
{
    size_t idx = (size_t)blockIdx.x * 256 + threadIdx.x;  // m*128 + blk
    size_t m = idx >> 7;
    int blk = (int)(idx & 127);
    const float* src = x + m * DD + blk * 16;
    float f[16];
    #pragma unroll
    for (int i = 0; i < 4; i++) {
        float4 v = *(const float4*)(src + i * 4);
        f[i*4+0] = v.x; f[i*4+1] = v.y; f[i*4+2] = v.z; f[i*4+3] = v.w;
    }
    float h[16], l[16];
    uint32_t hb[8];
    #pragma unroll
    for (int i = 0; i < 8; i++) {
        __nv_bfloat16 b0 = __float2bfloat16(f[2*i]);
        __nv_bfloat16 b1 = __float2bfloat16(f[2*i+1]);
        h[2*i]   = __bfloat162float(b0);
        h[2*i+1] = __bfloat162float(b1);
        l[2*i]   = f[2*i]   - h[2*i];
        l[2*i+1] = f[2*i+1] - h[2*i+1];
        __nv_bfloat162 p = __halves2bfloat162(b0, b1);
        hb[i] = *(uint32_t*)&p;
    }
    uint4* dsth = (uint4*)(g_xhi + m * DD + blk * 16);
    dsth[0] = make_uint4(hb[0], hb[1], hb[2], hb[3]);
    dsth[1] = make_uint4(hb[4], hb[5], hb[6], hb[7]);
    uint32_t lo8[4], hi8[4];
    #pragma unroll
    for (int i = 0; i < 4; i++) {
        lo8[i] = pack4_e4m3(l[4*i]*S_LO_X, l[4*i+1]*S_LO_X,
                            l[4*i+2]*S_LO_X, l[4*i+3]*S_LO_X);
        hi8[i] = pack4_e4m3(h[4*i], h[4*i+1], h[4*i+2], h[4*i+3]);
    }
    uint4* dst8 = (uint4*)(g_xc8 + m * (DD*2) + blk * 32);
    dst8[0] = make_uint4(lo8[0], lo8[1], lo8[2], lo8[3]);   // bytes 0-15: scaled lo
    dst8[1] = make_uint4(hi8[0], hi8[1], hi8[2], hi8[3]);   // bytes 16-31: hi
}

// ---------------------------------------------------------------------------
// Prepack W: bf16 hi + fp8 [32*hi | 131072*lo]
// ---------------------------------------------------------------------------
__global__ __launch_bounds__(256) void conv_w_kernel(
    const float* __restrict__ Wq, const float* __restrict__ Wk,
    const float* __restrict__ Wv, const float* __restrict__ Wg)
{
    int y = blockIdx.y;
    const float* W = (y == 0) ? Wq : (y == 1) ? Wk : (y == 2) ? Wv : Wg;
    size_t idx = (size_t)blockIdx.x * 256 + threadIdx.x;  // n*128 + blk
    size_t n = idx >> 7;
    int blk = (int)(idx & 127);
    const float* src = W + n * DD + blk * 16;
    float f[16];
    #pragma unroll
    for (int i = 0; i < 4; i++) {
        float4 v = *(const float4*)(src + i * 4);
        f[i*4+0] = v.x; f[i*4+1] = v.y; f[i*4+2] = v.z; f[i*4+3] = v.w;
    }
    float h[16], l[16];
    uint32_t hb[8];
    #pragma unroll
    for (int i = 0; i < 8; i++) {
        __nv_bfloat16 b0 = __float2bfloat16(f[2*i]);
        __nv_bfloat16 b1 = __float2bfloat16(f[2*i+1]);
        h[2*i]   = __bfloat162float(b0);
        h[2*i+1] = __bfloat162float(b1);
        l[2*i]   = f[2*i]   - h[2*i];
        l[2*i+1] = f[2*i+1] - h[2*i+1];
        __nv_bfloat162 p = __halves2bfloat162(b0, b1);
        hb[i] = *(uint32_t*)&p;
    }
    uint4* dsth = (uint4*)(g_whi + (size_t)y * DD * EE + n * DD + blk * 16);
    dsth[0] = make_uint4(hb[0], hb[1], hb[2], hb[3]);
    dsth[1] = make_uint4(hb[4], hb[5], hb[6], hb[7]);
    uint32_t hi8[4], lo8[4];
    #pragma unroll
    for (int i = 0; i < 4; i++) {
        hi8[i] = pack4_e4m3(h[4*i]*S_HI_W, h[4*i+1]*S_HI_W,
                            h[4*i+2]*S_HI_W, h[4*i+3]*S_HI_W);
        lo8[i] = pack4_e4m3(l[4*i]*S_LO_W, l[4*i+1]*S_LO_W,
                            l[4*i+2]*S_LO_W, l[4*i+3]*S_LO_W);
    }
    uint4* dst8 = (uint4*)(g_wc8 + (size_t)y * DD * EE * 2 + n * (DD*2) + blk * 32);
    dst8[0] = make_uint4(hi8[0], hi8[1], hi8[2], hi8[3]);   // bytes 0-15: scaled hi
    dst8[1] = make_uint4(lo8[0], lo8[1], lo8[2], lo8[3]);   // bytes 16-31: scaled lo
}

// ---------------------------------------------------------------------------
// GEMM: main term bf16 hi*hi (mma.m16n8k16) + corrections in ONE fp8 mma
// (m16n8k32, k-interleaved [lo_x|hi_x] x [hi_W|lo_W], composite scale 2^17).
// CTA 128x128, BK=64, 3-stage cp.async; warps 4(m) x 2(n); warp 32x64.
// z: 0=q, 1=k, 2=v, 3=g(sigmoid).
// ---------------------------------------------------------------------------
__global__ __launch_bounds__(256, 1) void gemm_mma(
    const float* __restrict__ bq, const float* __restrict__ bk,
    const float* __restrict__ bv, const float* __restrict__ bg)
{
    extern __shared__ char smem[];
    const uint32_t sb = smem_u32(smem);
    const int tid = threadIdx.x;
    const int wid = tid >> 5, lane = tid & 31;
    const int wm = wid >> 1, wn = wid & 1;           // warps 4(m) x 2(n)
    const int z = blockIdx.z;
    const size_t m0 = (size_t)blockIdx.y * Bb_M;
    const size_t n0 = (size_t)blockIdx.x * Bb_N;

    const float* bias = (z == 0) ? bq : (z == 1) ? bk : (z == 2) ? bv : bg;
    float* outp = (z == 0) ? g_q : (z == 1) ? g_k : (z == 2) ? g_v : g_g;

    // all four sources have 4096-byte rows
    const char* Ahi = (const char*)g_xhi + m0 * (DD * 2);
    const char* Acr = (const char*)g_xc8 + m0 * (DD * 2);
    const char* Bhi = (const char*)(g_whi + (size_t)z * DD * EE) + n0 * (DD * 2);
    const char* Bcr = (const char*)(g_wc8 + (size_t)z * DD * EE * 2) + n0 * (DD * 2);

    const int lrow = tid >> 3;        // 0..31
    const int lch  = tid & 7;         // 0..7

    auto load_stage = [&](int buf, int kb) {
        const uint32_t sbase = sb + buf * STAGE_BYTES;
        const size_t kbyte = (size_t)kb * 128;
        #pragma unroll
        for (int j = 0; j < 4; j++) {
            int row = lrow + j * 32;
            size_t goff = (size_t)row * (DD * 2) + kbyte + lch * 16;
            uint32_t soff = swz((uint32_t)row, (uint32_t)lch);
            cp_async16(sbase + AHI_OFF + soff, Ahi + goff);
            cp_async16(sbase + ACR_OFF + soff, Acr + goff);
            cp_async16(sbase + BHI_OFF + soff, Bhi + goff);
            cp_async16(sbase + BCR_OFF + soff, Bcr + goff);
        }
    };

    float accM[2][8][4], accC[2][8][4];
    #pragma unroll
    for (int mi = 0; mi < 2; mi++)
        #pragma unroll
        for (int ni = 0; ni < 8; ni++)
            #pragma unroll
            for (int e = 0; e < 4; e++) { accM[mi][ni][e] = 0.f; accC[mi][ni][e] = 0.f; }

    load_stage(0, 0); CP_COMMIT();
    load_stage(1, 1); CP_COMMIT();

    // ldmatrix lane->addr mappings (same pattern for bf16 and fp8 tiles)
    const uint32_t arow = (uint32_t)(wm * 32) + (uint32_t)(lane & 15); // + mi*16
    const uint32_t ahib = (uint32_t)(lane >> 4);
    const uint32_t brow = (uint32_t)(wn * 64) + (uint32_t)(lane & 7) +
                          (uint32_t)((lane & 16) >> 1);                // + g*16
    const uint32_t bhib = (uint32_t)((lane >> 3) & 1);

    for (int kb = 0; kb < KSTAGES; kb++) {
        if (kb + 1 < KSTAGES) { CP_WAIT1(); } else { CP_WAIT0(); }
        __syncthreads();
        if (kb + 2 < KSTAGES) { load_stage((kb + 2) % NSTAGE, kb + 2); CP_COMMIT(); }

        const uint32_t sbase = sb + (kb % NSTAGE) * STAGE_BYTES;
        #pragma unroll
        for (int kk = 0; kk < 4; kk++) {
            uint32_t ah[2][4], ac[2][4];
            #pragma unroll
            for (int mi = 0; mi < 2; mi++) {
                uint32_t off = swz(arow + mi * 16, kk * 2 + ahib);
                ldsm4(ah[mi], sbase + AHI_OFF + off);
                ldsm4(ac[mi], sbase + ACR_OFF + off);
            }
            #pragma unroll
            for (int g = 0; g < 4; g++) {
                uint32_t bh[4], bc[4];
                uint32_t off = swz(brow + g * 16, kk * 2 + bhib);
                ldsm4(bh, sbase + BHI_OFF + off);
                ldsm4(bc, sbase + BCR_OFF + off);
                #pragma unroll
                for (int mi = 0; mi < 2; mi++) {
                    #pragma unroll
                    for (int s = 0; s < 2; s++) {
                        int ni = g * 2 + s;
                        mma16816(accM[mi][ni], ah[mi], bh[s*2], bh[s*2+1]);
                        mma16832f8(accC[mi][ni], ac[mi], bc[s*2], bc[s*2+1]);
                    }
                }
            }
        }
    }

    // Epilogue: C = main + corr*2^-17 + bias (+ sigmoid for z==3)
    const int crow = lane >> 2;          // 0..7
    const int ccol = (lane & 3) * 2;     // 0,2,4,6
    #pragma unroll
    for (int ni = 0; ni < 8; ni++) {
        size_t n = n0 + wn * 64 + ni * 8 + ccol;
        float b0 = __ldg(bias + n), b1 = __ldg(bias + n + 1);
        #pragma unroll
        for (int mi = 0; mi < 2; mi++) {
            size_t m = m0 + wm * 32 + mi * 16 + crow;
            float2 o0, o1;
            o0.x = accM[mi][ni][0] + accC[mi][ni][0] * S_INV + b0;
            o0.y = accM[mi][ni][1] + accC[mi][ni][1] * S_INV + b1;
            o1.x = accM[mi][ni][2] + accC[mi][ni][2] * S_INV + b0;
            o1.y = accM[mi][ni][3] + accC[mi][ni][3] * S_INV + b1;
            if (z == 3) {
                o0.x = 1.f/(1.f+expf(-o0.x)); o0.y = 1.f/(1.f+expf(-o0.y));
                o1.x = 1.f/(1.f+expf(-o1.x)); o1.y = 1.f/(1.f+expf(-o1.y));
            }
            *(float2*)(outp + m * (size_t)EE + n) = o0;
            *(float2*)(outp + (m + 8) * (size_t)EE + n) = o1;
        }
    }
}

// ---------------------------------------------------------------------------
// Scan pass 1: per-chunk sums of k*v
// ---------------------------------------------------------------------------
__global__ __launch_bounds__(256) void chunk_sums()
{
    const int e = blockIdx.x * 256 + threadIdx.x;
    const int c = blockIdx.y;
    const int b = blockIdx.z;
    size_t idx = ((size_t)(b * SS + c * LCHUNK)) * EE + e;
    float s = 0.f;
    #pragma unroll 8
    for (int i = 0; i < LCHUNK; i++) {
        s += g_k[idx] * g_v[idx];
        idx += EE;
    }
    g_sums[((size_t)b * EE + e) * NCHUNK + c] = s;
}

// ---------------------------------------------------------------------------
// Scan pass 2: exclusive scan of chunk sums (in place)
// ---------------------------------------------------------------------------
__global__ __launch_bounds__(256) void scan_sums()
{
    const int t = blockIdx.x * 256 + threadIdx.x;
    float* p = g_sums + (size_t)t * NCHUNK;
    float v[NCHUNK];
    #pragma unroll
    for (int c = 0; c < NCHUNK; c++) v[c] = p[c];
    float run = 0.f;
    #pragma unroll
    for (int c = 0; c < NCHUNK; c++) { float t2 = v[c]; v[c] = run; run += t2; }
    #pragma unroll
    for (int c = 0; c < NCHUNK; c++) p[c] = v[c];
}

// ---------------------------------------------------------------------------
// Scan pass 3: local inclusive scan + q * state * g
// ---------------------------------------------------------------------------
__global__ __launch_bounds__(256) void finalize(float* __restrict__ out)
{
    const int e = blockIdx.x * 256 + threadIdx.x;
    const int c = blockIdx.y;
    const int b = blockIdx.z;
    float run = g_sums[((size_t)b * EE + e) * NCHUNK + c];
    size_t idx = ((size_t)(b * SS + c * LCHUNK)) * EE + e;
    #pragma unroll 4
    for (int i = 0; i < LCHUNK; i++) {
        run += g_k[idx] * g_v[idx];
        out[idx] = g_q[idx] * run * g_g[idx];
        idx += EE;
    }
}

// ---------------------------------------------------------------------------
// Launch
// ---------------------------------------------------------------------------
extern "C" void kernel_launch(void* const* d_in, const int* in_sizes, int n_in,
                              void* d_out, int out_size)
{
    const float* x  = (const float*)d_in[0];
    const float* Wq = (const float*)d_in[1];
    const float* bq = (const float*)d_in[2];
    const float* Wk = (const float*)d_in[3];
    const float* bk = (const float*)d_in[4];
    const float* Wv = (const float*)d_in[5];
    const float* bv = (const float*)d_in[6];
    const float* Wg = (const float*)d_in[7];
    const float* bg = (const float*)d_in[8];
    float* out = (float*)d_out;

    cudaFuncSetAttribute(gemm_mma,
        cudaFuncAttributeMaxDynamicSharedMemorySize, SMEM_TOTAL);

    conv_x_kernel<<<(MM * (DD/16)) / 256, 256>>>(x);
    conv_w_kernel<<<dim3((EE * (DD/16)) / 256, 4), 256>>>(Wq, Wk, Wv, Wg);

    gemm_mma<<<dim3(EE/Bb_N, MM/Bb_M, 4), 256, SMEM_TOTAL>>>(bq, bk, bv, bg);

    dim3 gridC(EE / 256, NCHUNK, BB);
    chunk_sums<<<gridC, 256>>>();
    scan_sums<<<(BB * EE) / 256, 256>>>();
    finalize<<<gridC, 256>>>(out);
}

// round 7
// speedup vs baseline: 2.7487x; 2.7487x over previous
#include <cuda_runtime.h>
#include <cuda_fp16.h>
#include <cstdint>
#include <math.h>

// ---------------------------------------------------------------------------
// Problem dims
// ---------------------------------------------------------------------------
#define BB 4
#define SS 4096
#define DD 2048
#define EE 2048
#define MM (BB*SS)         // 16384
#define NCHUNK 64
#define LCHUNK (SS/NCHUNK) // 64

// GEMM tiling: CTA 256x128, BK=64, warps 4(m) x 2(n), warp tile 64x64
#define Bb_M 256
#define Bb_N 128
#define Bb_K 64
#define KSTAGES (DD/Bb_K)  // 32

// Stage smem (bytes): A 256 rows x 128B, B 128 rows x 128B   (fp16, BK=64)
#define A_OFF 0
#define B_OFF 32768
#define STAGE_BYTES 49152
#define NSTAGE 3
#define SMEM_TOTAL (NSTAGE*STAGE_BYTES)   // 147456

// ---------------------------------------------------------------------------
// Device scratch
// ---------------------------------------------------------------------------
__device__ __half g_xh[(size_t)MM * DD];          // 64 MB fp16 x
__device__ __half g_wh[(size_t)4 * DD * EE];      // 32 MB fp16 W (q,k,v,g)
__device__ float g_q[(size_t)MM * EE];
__device__ float g_k[(size_t)MM * EE];
__device__ float g_v[(size_t)MM * EE];
__device__ float g_g[(size_t)MM * EE];
__device__ float g_sums[(size_t)BB * EE * NCHUNK];

// ---------------------------------------------------------------------------
// Helpers (sm_80-era instructions only — compile at compute_103 baseline)
// ---------------------------------------------------------------------------
__device__ __forceinline__ uint32_t smem_u32(const void* p) {
    uint32_t a;
    asm("{ .reg .u64 t; cvta.to.shared.u64 t, %1; cvt.u32.u64 %0, t; }"
        : "=r"(a) : "l"(p));
    return a;
}
__device__ __forceinline__ void cp_async16(uint32_t dst, const void* src) {
    asm volatile("cp.async.cg.shared.global [%0], [%1], 16;"
                 :: "r"(dst), "l"(src) : "memory");
}
#define CP_COMMIT() asm volatile("cp.async.commit_group;" ::: "memory")
#define CP_WAIT1()  asm volatile("cp.async.wait_group 1;" ::: "memory")
#define CP_WAIT0()  asm volatile("cp.async.wait_group 0;" ::: "memory")

__device__ __forceinline__ void ldsm4(uint32_t (&r)[4], uint32_t addr) {
    asm volatile("ldmatrix.sync.aligned.m8n8.x4.shared.b16 {%0,%1,%2,%3}, [%4];"
                 : "=r"(r[0]), "=r"(r[1]), "=r"(r[2]), "=r"(r[3]) : "r"(addr));
}
__device__ __forceinline__ void mma16816h(float (&c)[4], const uint32_t (&a)[4],
                                          uint32_t b0, uint32_t b1) {
    asm volatile("mma.sync.aligned.m16n8k16.row.col.f32.f16.f16.f32 "
                 "{%0,%1,%2,%3}, {%4,%5,%6,%7}, {%8,%9}, {%0,%1,%2,%3};"
                 : "+f"(c[0]), "+f"(c[1]), "+f"(c[2]), "+f"(c[3])
                 : "r"(a[0]), "r"(a[1]), "r"(a[2]), "r"(a[3]), "r"(b0), "r"(b1));
}
// SW128 swizzled byte offset inside a [row][128B] tile
__device__ __forceinline__ uint32_t swz(uint32_t row, uint32_t ch) {
    return row * 128u + (((ch ^ (row & 7u)) & 7u) << 4);
}

// ---------------------------------------------------------------------------
// fp32 -> fp16 conversions (8 elems/thread)
// ---------------------------------------------------------------------------
__global__ __launch_bounds__(256) void conv_x_kernel(const float* __restrict__ x)
{
    size_t i = ((size_t)blockIdx.x * 256 + threadIdx.x) * 8;
    float4 v0 = *(const float4*)(x + i);
    float4 v1 = *(const float4*)(x + i + 4);
    __half2 h[4];
    h[0] = __floats2half2_rn(v0.x, v0.y);
    h[1] = __floats2half2_rn(v0.z, v0.w);
    h[2] = __floats2half2_rn(v1.x, v1.y);
    h[3] = __floats2half2_rn(v1.z, v1.w);
    *(uint4*)(g_xh + i) = *(uint4*)h;
}

__global__ __launch_bounds__(256) void conv_w_kernel(
    const float* __restrict__ Wq, const float* __restrict__ Wk,
    const float* __restrict__ Wv, const float* __restrict__ Wg)
{
    int y = blockIdx.y;
    const float* W = (y == 0) ? Wq : (y == 1) ? Wk : (y == 2) ? Wv : Wg;
    size_t i = ((size_t)blockIdx.x * 256 + threadIdx.x) * 8;
    float4 v0 = *(const float4*)(W + i);
    float4 v1 = *(const float4*)(W + i + 4);
    __half2 h[4];
    h[0] = __floats2half2_rn(v0.x, v0.y);
    h[1] = __floats2half2_rn(v0.z, v0.w);
    h[2] = __floats2half2_rn(v1.x, v1.y);
    h[3] = __floats2half2_rn(v1.z, v1.w);
    *(uint4*)(g_wh + (size_t)y * DD * EE + i) = *(uint4*)h;
}

// ---------------------------------------------------------------------------
// fp16 GEMM on mma.sync.  C[m,n] = x[m,:] . W_z[n,:] + b_z[n]
// z: 0=q, 1=k, 2=v, 3=g(sigmoid).
// CTA 256x128, BK=64, 3-stage cp.async; warps 4(m) x 2(n); warp tile 64x64.
// ---------------------------------------------------------------------------
__global__ __launch_bounds__(256, 1) void gemm_mma(
    const float* __restrict__ bq, const float* __restrict__ bk,
    const float* __restrict__ bv, const float* __restrict__ bg)
{
    extern __shared__ char smem[];
    const uint32_t sb = smem_u32(smem);
    const int tid = threadIdx.x;
    const int wid = tid >> 5, lane = tid & 31;
    const int wm = wid >> 1, wn = wid & 1;           // warps 4(m) x 2(n)
    const int z = blockIdx.z;
    const size_t m0 = (size_t)blockIdx.y * Bb_M;
    const size_t n0 = (size_t)blockIdx.x * Bb_N;

    const float* bias = (z == 0) ? bq : (z == 1) ? bk : (z == 2) ? bv : bg;
    float* outp = (z == 0) ? g_q : (z == 1) ? g_k : (z == 2) ? g_v : g_g;

    const char* Ag = (const char*)g_xh + m0 * (DD * 2);
    const char* Bg = (const char*)(g_wh + (size_t)z * DD * EE) + n0 * (DD * 2);

    const int lrow = tid >> 3;        // 0..31
    const int lch  = tid & 7;         // 0..7

    auto load_stage = [&](int buf, int kb) {
        const uint32_t sbase = sb + buf * STAGE_BYTES;
        const size_t kbyte = (size_t)kb * 128;
        #pragma unroll
        for (int j = 0; j < 8; j++) {          // A: 256 rows
            int row = lrow + j * 32;
            size_t goff = (size_t)row * (DD * 2) + kbyte + lch * 16;
            cp_async16(sbase + A_OFF + swz((uint32_t)row, (uint32_t)lch), Ag + goff);
        }
        #pragma unroll
        for (int j = 0; j < 4; j++) {          // B: 128 rows
            int row = lrow + j * 32;
            size_t goff = (size_t)row * (DD * 2) + kbyte + lch * 16;
            cp_async16(sbase + B_OFF + swz((uint32_t)row, (uint32_t)lch), Bg + goff);
        }
    };

    float acc[4][8][4];   // [mi][ni = g*2+s][frag]
    #pragma unroll
    for (int mi = 0; mi < 4; mi++)
        #pragma unroll
        for (int ni = 0; ni < 8; ni++)
            #pragma unroll
            for (int e = 0; e < 4; e++) acc[mi][ni][e] = 0.f;

    load_stage(0, 0); CP_COMMIT();
    load_stage(1, 1); CP_COMMIT();

    // ldmatrix lane->addr mapping
    const uint32_t arow = (uint32_t)(wm * 64) + (uint32_t)(lane & 15); // + mi*16
    const uint32_t ahib = (uint32_t)(lane >> 4);
    const uint32_t brow = (uint32_t)(wn * 64) + (uint32_t)(lane & 7) +
                          (uint32_t)((lane & 16) >> 1);                // + g*16
    const uint32_t bhib = (uint32_t)((lane >> 3) & 1);

    for (int kb = 0; kb < KSTAGES; kb++) {
        if (kb + 1 < KSTAGES) { CP_WAIT1(); } else { CP_WAIT0(); }
        __syncthreads();
        if (kb + 2 < KSTAGES) { load_stage((kb + 2) % NSTAGE, kb + 2); CP_COMMIT(); }

        const uint32_t sbase = sb + (kb % NSTAGE) * STAGE_BYTES;
        #pragma unroll
        for (int kk = 0; kk < 4; kk++) {
            uint32_t af[4][4];
            #pragma unroll
            for (int mi = 0; mi < 4; mi++) {
                uint32_t off = swz(arow + mi * 16, kk * 2 + ahib);
                ldsm4(af[mi], sbase + A_OFF + off);
            }
            #pragma unroll
            for (int g = 0; g < 4; g++) {       // stream B frags per 16-col group
                uint32_t bf[4];
                uint32_t off = swz(brow + g * 16, kk * 2 + bhib);
                ldsm4(bf, sbase + B_OFF + off);
                #pragma unroll
                for (int mi = 0; mi < 4; mi++) {
                    #pragma unroll
                    for (int s = 0; s < 2; s++) {
                        mma16816h(acc[mi][g*2+s], af[mi], bf[s*2], bf[s*2+1]);
                    }
                }
            }
        }
    }

    // Epilogue: bias (+ sigmoid for z==3), float2 stores
    const int crow = lane >> 2;          // 0..7
    const int ccol = (lane & 3) * 2;     // 0,2,4,6
    #pragma unroll
    for (int ni = 0; ni < 8; ni++) {
        size_t n = n0 + wn * 64 + ni * 8 + ccol;
        float b0 = __ldg(bias + n), b1 = __ldg(bias + n + 1);
        #pragma unroll
        for (int mi = 0; mi < 4; mi++) {
            size_t m = m0 + wm * 64 + mi * 16 + crow;
            float2 o0 = make_float2(acc[mi][ni][0] + b0, acc[mi][ni][1] + b1);
            float2 o1 = make_float2(acc[mi][ni][2] + b0, acc[mi][ni][3] + b1);
            if (z == 3) {
                o0.x = 1.f/(1.f+expf(-o0.x)); o0.y = 1.f/(1.f+expf(-o0.y));
                o1.x = 1.f/(1.f+expf(-o1.x)); o1.y = 1.f/(1.f+expf(-o1.y));
            }
            *(float2*)(outp + m * (size_t)EE + n) = o0;
            *(float2*)(outp + (m + 8) * (size_t)EE + n) = o1;
        }
    }
}

// ---------------------------------------------------------------------------
// Scan pass 1: per-chunk sums of k*v
// ---------------------------------------------------------------------------
__global__ __launch_bounds__(256) void chunk_sums()
{
    const int e = blockIdx.x * 256 + threadIdx.x;
    const int c = blockIdx.y;
    const int b = blockIdx.z;
    size_t idx = ((size_t)(b * SS + c * LCHUNK)) * EE + e;
    float s = 0.f;
    #pragma unroll 8
    for (int i = 0; i < LCHUNK; i++) {
        s += g_k[idx] * g_v[idx];
        idx += EE;
    }
    g_sums[((size_t)b * EE + e) * NCHUNK + c] = s;
}

// ---------------------------------------------------------------------------
// Scan pass 2: exclusive scan of chunk sums (in place)
// ---------------------------------------------------------------------------
__global__ __launch_bounds__(256) void scan_sums()
{
    const int t = blockIdx.x * 256 + threadIdx.x;
    float* p = g_sums + (size_t)t * NCHUNK;
    float v[NCHUNK];
    #pragma unroll
    for (int c = 0; c < NCHUNK; c++) v[c] = p[c];
    float run = 0.f;
    #pragma unroll
    for (int c = 0; c < NCHUNK; c++) { float t2 = v[c]; v[c] = run; run += t2; }
    #pragma unroll
    for (int c = 0; c < NCHUNK; c++) p[c] = v[c];
}

// ---------------------------------------------------------------------------
// Scan pass 3: local inclusive scan + q * state * g
// ---------------------------------------------------------------------------
__global__ __launch_bounds__(256) void finalize(float* __restrict__ out)
{
    const int e = blockIdx.x * 256 + threadIdx.x;
    const int c = blockIdx.y;
    const int b = blockIdx.z;
    float run = g_sums[((size_t)b * EE + e) * NCHUNK + c];
    size_t idx = ((size_t)(b * SS + c * LCHUNK)) * EE + e;
    #pragma unroll 4
    for (int i = 0; i < LCHUNK; i++) {
        run += g_k[idx] * g_v[idx];
        out[idx] = g_q[idx] * run * g_g[idx];
        idx += EE;
    }
}

// ---------------------------------------------------------------------------
// Launch
// ---------------------------------------------------------------------------
extern "C" void kernel_launch(void* const* d_in, const int* in_sizes, int n_in,
                              void* d_out, int out_size)
{
    const float* x  = (const float*)d_in[0];
    const float* Wq = (const float*)d_in[1];
    const float* bq = (const float*)d_in[2];
    const float* Wk = (const float*)d_in[3];
    const float* bk = (const float*)d_in[4];
    const float* Wv = (const float*)d_in[5];
    const float* bv = (const float*)d_in[6];
    const float* Wg = (const float*)d_in[7];
    const float* bg = (const float*)d_in[8];
    float* out = (float*)d_out;

    cudaFuncSetAttribute(gemm_mma,
        cudaFuncAttributeMaxDynamicSharedMemorySize, SMEM_TOTAL);

    conv_x_kernel<<<(MM * (size_t)DD / 8) / 256, 256>>>(x);
    conv_w_kernel<<<dim3((DD * (size_t)EE / 8) / 256, 4), 256>>>(Wq, Wk, Wv, Wg);

    gemm_mma<<<dim3(EE/Bb_N, MM/Bb_M, 4), 256, SMEM_TOTAL>>>(bq, bk, bv, bg);

    dim3 gridC(EE / 256, NCHUNK, BB);
    chunk_sums<<<gridC, 256>>>();
    scan_sums<<<(BB * EE) / 256, 256>>>();
    finalize<<<gridC, 256>>>(out);
}

// round 8
// speedup vs baseline: 3.0219x; 1.0994x over previous
#include <cuda_runtime.h>
#include <cuda_fp16.h>
#include <cstdint>
#include <math.h>

// ---------------------------------------------------------------------------
// Problem dims
// ---------------------------------------------------------------------------
#define BB 4
#define SS 4096
#define DD 2048
#define EE 2048
#define MM (BB*SS)         // 16384
#define NCHUNK 64
#define LCHUNK (SS/NCHUNK) // 64

// GEMM tiling: CTA 128x128, BK=64, warps 2(m) x 4(n), warp tile 64x32
#define Bb_M 128
#define Bb_N 128
#define Bb_K 64
#define KSTAGES (DD/Bb_K)  // 32

// Stage smem (bytes): A 128 rows x 128B, B 128 rows x 128B  (fp16, BK=64)
#define A_OFF 0
#define B_OFF 16384
#define STAGE_BYTES 32768
#define NSTAGE 3
#define SMEM_TOTAL (NSTAGE*STAGE_BYTES)   // 98304  -> 2 CTAs/SM
// ---------------------------------------------------------------------------
// Device scratch
// ---------------------------------------------------------------------------
__device__ __half g_xh[(size_t)MM * DD];          // 64 MB fp16 x
__device__ __half g_wh[(size_t)4 * DD * EE];      // 32 MB fp16 W (q,k,v,g)
__device__ float g_q[(size_t)MM * EE];
__device__ float g_k[(size_t)MM * EE];
__device__ float g_v[(size_t)MM * EE];
__device__ float g_g[(size_t)MM * EE];
__device__ float g_sums[(size_t)BB * EE * NCHUNK];

// ---------------------------------------------------------------------------
// Helpers (sm_80-era instructions only — compile at compute_103 baseline)
// ---------------------------------------------------------------------------
__device__ __forceinline__ uint32_t smem_u32(const void* p) {
    uint32_t a;
    asm("{ .reg .u64 t; cvta.to.shared.u64 t, %1; cvt.u32.u64 %0, t; }"
        : "=r"(a) : "l"(p));
    return a;
}
__device__ __forceinline__ void cp_async16(uint32_t dst, const void* src) {
    asm volatile("cp.async.cg.shared.global [%0], [%1], 16;"
                 :: "r"(dst), "l"(src) : "memory");
}
#define CP_COMMIT() asm volatile("cp.async.commit_group;" ::: "memory")
#define CP_WAIT1()  asm volatile("cp.async.wait_group 1;" ::: "memory")
#define CP_WAIT0()  asm volatile("cp.async.wait_group 0;" ::: "memory")

__device__ __forceinline__ void ldsm4(uint32_t (&r)[4], uint32_t addr) {
    asm volatile("ldmatrix.sync.aligned.m8n8.x4.shared.b16 {%0,%1,%2,%3}, [%4];"
                 : "=r"(r[0]), "=r"(r[1]), "=r"(r[2]), "=r"(r[3]) : "r"(addr));
}
__device__ __forceinline__ void mma16816h(float (&c)[4], const uint32_t (&a)[4],
                                          uint32_t b0, uint32_t b1) {
    asm volatile("mma.sync.aligned.m16n8k16.row.col.f32.f16.f16.f32 "
                 "{%0,%1,%2,%3}, {%4,%5,%6,%7}, {%8,%9}, {%0,%1,%2,%3};"
                 : "+f"(c[0]), "+f"(c[1]), "+f"(c[2]), "+f"(c[3])
                 : "r"(a[0]), "r"(a[1]), "r"(a[2]), "r"(a[3]), "r"(b0), "r"(b1));
}
// SW128 swizzled byte offset inside a [row][128B] tile
__device__ __forceinline__ uint32_t swz(uint32_t row, uint32_t ch) {
    return row * 128u + (((ch ^ (row & 7u)) & 7u) << 4);
}

// ---------------------------------------------------------------------------
// fp32 -> fp16 conversions (8 elems/thread)
// ---------------------------------------------------------------------------
__global__ __launch_bounds__(256) void conv_x_kernel(const float* __restrict__ x)
{
    size_t i = ((size_t)blockIdx.x * 256 + threadIdx.x) * 8;
    float4 v0 = *(const float4*)(x + i);
    float4 v1 = *(const float4*)(x + i + 4);
    __half2 h[4];
    h[0] = __floats2half2_rn(v0.x, v0.y);
    h[1] = __floats2half2_rn(v0.z, v0.w);
    h[2] = __floats2half2_rn(v1.x, v1.y);
    h[3] = __floats2half2_rn(v1.z, v1.w);
    *(uint4*)(g_xh + i) = *(uint4*)h;
}

__global__ __launch_bounds__(256) void conv_w_kernel(
    const float* __restrict__ Wq, const float* __restrict__ Wk,
    const float* __restrict__ Wv, const float* __restrict__ Wg)
{
    int y = blockIdx.y;
    const float* W = (y == 0) ? Wq : (y == 1) ? Wk : (y == 2) ? Wv : Wg;
    size_t i = ((size_t)blockIdx.x * 256 + threadIdx.x) * 8;
    float4 v0 = *(const float4*)(W + i);
    float4 v1 = *(const float4*)(W + i + 4);
    __half2 h[4];
    h[0] = __floats2half2_rn(v0.x, v0.y);
    h[1] = __floats2half2_rn(v0.z, v0.w);
    h[2] = __floats2half2_rn(v1.x, v1.y);
    h[3] = __floats2half2_rn(v1.z, v1.w);
    *(uint4*)(g_wh + (size_t)y * DD * EE + i) = *(uint4*)h;
}

// ---------------------------------------------------------------------------
// fp16 GEMM on mma.sync.  C[m,n] = x[m,:] . W_z[n,:] + b_z[n]
// z: 0=q, 1=k, 2=v, 3=g(sigmoid).
// CTA 128x128, BK=64, 3-stage cp.async; warps 2(m) x 4(n); warp tile 64x32.
// 96KB smem -> 2 CTAs/SM -> 4 warps/SMSP to fill MMA issue slots.
// ---------------------------------------------------------------------------
__global__ __launch_bounds__(256, 2) void gemm_mma(
    const float* __restrict__ bq, const float* __restrict__ bk,
    const float* __restrict__ bv, const float* __restrict__ bg)
{
    extern __shared__ char smem[];
    const uint32_t sb = smem_u32(smem);
    const int tid = threadIdx.x;
    const int wid = tid >> 5, lane = tid & 31;
    const int wm = wid >> 2, wn = wid & 3;           // warps 2(m) x 4(n)
    const int z = blockIdx.z;
    const size_t m0 = (size_t)blockIdx.y * Bb_M;
    const size_t n0 = (size_t)blockIdx.x * Bb_N;

    const float* bias = (z == 0) ? bq : (z == 1) ? bk : (z == 2) ? bv : bg;
    float* outp = (z == 0) ? g_q : (z == 1) ? g_k : (z == 2) ? g_v : g_g;

    const char* Ag = (const char*)g_xh + m0 * (DD * 2);
    const char* Bg = (const char*)(g_wh + (size_t)z * DD * EE) + n0 * (DD * 2);

    const int lrow = tid >> 3;        // 0..31
    const int lch  = tid & 7;         // 0..7

    auto load_stage = [&](int buf, int kb) {
        const uint32_t sbase = sb + buf * STAGE_BYTES;
        const size_t kbyte = (size_t)kb * 128;
        #pragma unroll
        for (int j = 0; j < 4; j++) {          // A: 128 rows
            int row = lrow + j * 32;
            size_t goff = (size_t)row * (DD * 2) + kbyte + lch * 16;
            cp_async16(sbase + A_OFF + swz((uint32_t)row, (uint32_t)lch), Ag + goff);
        }
        #pragma unroll
        for (int j = 0; j < 4; j++) {          // B: 128 rows
            int row = lrow + j * 32;
            size_t goff = (size_t)row * (DD * 2) + kbyte + lch * 16;
            cp_async16(sbase + B_OFF + swz((uint32_t)row, (uint32_t)lch), Bg + goff);
        }
    };

    float acc[4][4][4];   // [mi][ni = g*2+s][frag]
    #pragma unroll
    for (int mi = 0; mi < 4; mi++)
        #pragma unroll
        for (int ni = 0; ni < 4; ni++)
            #pragma unroll
            for (int e = 0; e < 4; e++) acc[mi][ni][e] = 0.f;

    load_stage(0, 0); CP_COMMIT();
    load_stage(1, 1); CP_COMMIT();

    // ldmatrix lane->addr mapping
    const uint32_t arow = (uint32_t)(wm * 64) + (uint32_t)(lane & 15); // + mi*16
    const uint32_t ahib = (uint32_t)(lane >> 4);
    const uint32_t brow = (uint32_t)(wn * 32) + (uint32_t)(lane & 7) +
                          (uint32_t)((lane & 16) >> 1);                // + g*16
    const uint32_t bhib = (uint32_t)((lane >> 3) & 1);

    for (int kb = 0; kb < KSTAGES; kb++) {
        if (kb + 1 < KSTAGES) { CP_WAIT1(); } else { CP_WAIT0(); }
        __syncthreads();
        if (kb + 2 < KSTAGES) { load_stage((kb + 2) % NSTAGE, kb + 2); CP_COMMIT(); }

        const uint32_t sbase = sb + (kb % NSTAGE) * STAGE_BYTES;
        #pragma unroll
        for (int kk = 0; kk < 4; kk++) {
            uint32_t af[4][4];
            #pragma unroll
            for (int mi = 0; mi < 4; mi++) {
                uint32_t off = swz(arow + mi * 16, kk * 2 + ahib);
                ldsm4(af[mi], sbase + A_OFF + off);
            }
            #pragma unroll
            for (int g = 0; g < 2; g++) {      // B frags per 16-col group
                uint32_t bf[4];
                uint32_t off = swz(brow + g * 16, kk * 2 + bhib);
                ldsm4(bf, sbase + B_OFF + off);
                #pragma unroll
                for (int mi = 0; mi < 4; mi++) {
                    #pragma unroll
                    for (int s = 0; s < 2; s++) {
                        mma16816h(acc[mi][g*2+s], af[mi], bf[s*2], bf[s*2+1]);
                    }
                }
            }
        }
    }

    // Epilogue: bias (+ sigmoid for z==3), float2 stores
    const int crow = lane >> 2;          // 0..7
    const int ccol = (lane & 3) * 2;     // 0,2,4,6
    #pragma unroll
    for (int ni = 0; ni < 4; ni++) {
        size_t n = n0 + wn * 32 + ni * 8 + ccol;
        float b0 = __ldg(bias + n), b1 = __ldg(bias + n + 1);
        #pragma unroll
        for (int mi = 0; mi < 4; mi++) {
            size_t m = m0 + wm * 64 + mi * 16 + crow;
            float2 o0 = make_float2(acc[mi][ni][0] + b0, acc[mi][ni][1] + b1);
            float2 o1 = make_float2(acc[mi][ni][2] + b0, acc[mi][ni][3] + b1);
            if (z == 3) {
                o0.x = 1.f/(1.f+expf(-o0.x)); o0.y = 1.f/(1.f+expf(-o0.y));
                o1.x = 1.f/(1.f+expf(-o1.x)); o1.y = 1.f/(1.f+expf(-o1.y));
            }
            *(float2*)(outp + m * (size_t)EE + n) = o0;
            *(float2*)(outp + (m + 8) * (size_t)EE + n) = o1;
        }
    }
}

// ---------------------------------------------------------------------------
// Scan pass 1: per-chunk sums of k*v
// ---------------------------------------------------------------------------
__global__ __launch_bounds__(256) void chunk_sums()
{
    const int e = blockIdx.x * 256 + threadIdx.x;
    const int c = blockIdx.y;
    const int b = blockIdx.z;
    size_t idx = ((size_t)(b * SS + c * LCHUNK)) * EE + e;
    float s = 0.f;
    #pragma unroll 8
    for (int i = 0; i < LCHUNK; i++) {
        s += g_k[idx] * g_v[idx];
        idx += EE;
    }
    g_sums[((size_t)b * EE + e) * NCHUNK + c] = s;
}

// ---------------------------------------------------------------------------
// Scan pass 2: exclusive scan of chunk sums (in place)
// ---------------------------------------------------------------------------
__global__ __launch_bounds__(256) void scan_sums()
{
    const int t = blockIdx.x * 256 + threadIdx.x;
    float* p = g_sums + (size_t)t * NCHUNK;
    float v[NCHUNK];
    #pragma unroll
    for (int c = 0; c < NCHUNK; c++) v[c] = p[c];
    float run = 0.f;
    #pragma unroll
    for (int c = 0; c < NCHUNK; c++) { float t2 = v[c]; v[c] = run; run += t2; }
    #pragma unroll
    for (int c = 0; c < NCHUNK; c++) p[c] = v[c];
}

// ---------------------------------------------------------------------------
// Scan pass 3: local inclusive scan + q * state * g
// ---------------------------------------------------------------------------
__global__ __launch_bounds__(256) void finalize(float* __restrict__ out)
{
    const int e = blockIdx.x * 256 + threadIdx.x;
    const int c = blockIdx.y;
    const int b = blockIdx.z;
    float run = g_sums[((size_t)b * EE + e) * NCHUNK + c];
    size_t idx = ((size_t)(b * SS + c * LCHUNK)) * EE + e;
    #pragma unroll 4
    for (int i = 0; i < LCHUNK; i++) {
        run += g_k[idx] * g_v[idx];
        out[idx] = g_q[idx] * run * g_g[idx];
        idx += EE;
    }
}

// ---------------------------------------------------------------------------
// Launch
// ---------------------------------------------------------------------------
extern "C" void kernel_launch(void* const* d_in, const int* in_sizes, int n_in,
                              void* d_out, int out_size)
{
    const float* x  = (const float*)d_in[0];
    const float* Wq = (const float*)d_in[1];
    const float* bq = (const float*)d_in[2];
    const float* Wk = (const float*)d_in[3];
    const float* bk = (const float*)d_in[4];
    const float* Wv = (const float*)d_in[5];
    const float* bv = (const float*)d_in[6];
    const float* Wg = (const float*)d_in[7];
    const float* bg = (const float*)d_in[8];
    float* out = (float*)d_out;

    cudaFuncSetAttribute(gemm_mma,
        cudaFuncAttributeMaxDynamicSharedMemorySize, SMEM_TOTAL);

    conv_x_kernel<<<(MM * (size_t)DD / 8) / 256, 256>>>(x);
    conv_w_kernel<<<dim3((DD * (size_t)EE / 8) / 256, 4), 256>>>(Wq, Wk, Wv, Wg);

    gemm_mma<<<dim3(EE/Bb_N, MM/Bb_M, 4), 256, SMEM_TOTAL>>>(bq, bk, bv, bg);

    dim3 gridC(EE / 256, NCHUNK, BB);
    chunk_sums<<<gridC, 256>>>();
    scan_sums<<<(BB * EE) / 256, 256>>>();
    finalize<<<gridC, 256>>>(out);
}

// round 9
// speedup vs baseline: 3.2683x; 1.0815x over previous
#include <cuda_runtime.h>
#include <cuda_fp16.h>
#include <cstdint>
#include <math.h>

// ---------------------------------------------------------------------------
// Problem dims
// ---------------------------------------------------------------------------
#define BB 4
#define SS 4096
#define DD 2048
#define EE 2048
#define MM (BB*SS)         // 16384
#define NCHUNK 64
#define LCHUNK (SS/NCHUNK) // 64

// GEMM tiling: CTA covers M=128 x N=64, TWO outputs per CTA (paired weights).
// BK=64, warps 2(m) x 4(n), warp tile 64m x 16n per output.
#define Bb_M 128
#define Bb_N 64
#define Bb_K 64
#define KSTAGES (DD/Bb_K)  // 32

// Stage smem (bytes): A 128 rows x 128B, B 128 rows (64 per weight) x 128B
#define A_OFF 0
#define B_OFF 16384
#define STAGE_BYTES 32768
#define NSTAGE 3
#define SMEM_TOTAL (NSTAGE*STAGE_BYTES)   // 98304 -> 2 CTAs/SM

// ---------------------------------------------------------------------------
// Device scratch
// ---------------------------------------------------------------------------
__device__ __half g_xh[(size_t)MM * DD];          // 64 MB fp16 x
__device__ __half g_wh[(size_t)4 * DD * EE];      // 32 MB fp16 W (q,k,v,g)
__device__ float g_qg[(size_t)MM * EE];           // 128 MB  q * sigmoid(g)
__device__ float g_kv[(size_t)MM * EE];           // 128 MB  k * v
__device__ float g_sums[(size_t)BB * EE * NCHUNK];

// ---------------------------------------------------------------------------
// Helpers (sm_80-era instructions only — compile at compute_103 baseline)
// ---------------------------------------------------------------------------
__device__ __forceinline__ uint32_t smem_u32(const void* p) {
    uint32_t a;
    asm("{ .reg .u64 t; cvta.to.shared.u64 t, %1; cvt.u32.u64 %0, t; }"
        : "=r"(a) : "l"(p));
    return a;
}
__device__ __forceinline__ void cp_async16(uint32_t dst, const void* src) {
    asm volatile("cp.async.cg.shared.global [%0], [%1], 16;"
                 :: "r"(dst), "l"(src) : "memory");
}
#define CP_COMMIT() asm volatile("cp.async.commit_group;" ::: "memory")
#define CP_WAIT1()  asm volatile("cp.async.wait_group 1;" ::: "memory")
#define CP_WAIT0()  asm volatile("cp.async.wait_group 0;" ::: "memory")

__device__ __forceinline__ void ldsm4(uint32_t (&r)[4], uint32_t addr) {
    asm volatile("ldmatrix.sync.aligned.m8n8.x4.shared.b16 {%0,%1,%2,%3}, [%4];"
                 : "=r"(r[0]), "=r"(r[1]), "=r"(r[2]), "=r"(r[3]) : "r"(addr));
}
__device__ __forceinline__ void mma16816h(float (&c)[4], const uint32_t (&a)[4],
                                          uint32_t b0, uint32_t b1) {
    asm volatile("mma.sync.aligned.m16n8k16.row.col.f32.f16.f16.f32 "
                 "{%0,%1,%2,%3}, {%4,%5,%6,%7}, {%8,%9}, {%0,%1,%2,%3};"
                 : "+f"(c[0]), "+f"(c[1]), "+f"(c[2]), "+f"(c[3])
                 : "r"(a[0]), "r"(a[1]), "r"(a[2]), "r"(a[3]), "r"(b0), "r"(b1));
}
// SW128 swizzled byte offset inside a [row][128B] tile
__device__ __forceinline__ uint32_t swz(uint32_t row, uint32_t ch) {
    return row * 128u + (((ch ^ (row & 7u)) & 7u) << 4);
}

// ---------------------------------------------------------------------------
// fp32 -> fp16 conversions (8 elems/thread)
// ---------------------------------------------------------------------------
__global__ __launch_bounds__(256) void conv_x_kernel(const float* __restrict__ x)
{
    size_t i = ((size_t)blockIdx.x * 256 + threadIdx.x) * 8;
    float4 v0 = *(const float4*)(x + i);
    float4 v1 = *(const float4*)(x + i + 4);
    __half2 h[4];
    h[0] = __floats2half2_rn(v0.x, v0.y);
    h[1] = __floats2half2_rn(v0.z, v0.w);
    h[2] = __floats2half2_rn(v1.x, v1.y);
    h[3] = __floats2half2_rn(v1.z, v1.w);
    *(uint4*)(g_xh + i) = *(uint4*)h;
}

__global__ __launch_bounds__(256) void conv_w_kernel(
    const float* __restrict__ Wq, const float* __restrict__ Wk,
    const float* __restrict__ Wv, const float* __restrict__ Wg)
{
    int y = blockIdx.y;
    const float* W = (y == 0) ? Wq : (y == 1) ? Wk : (y == 2) ? Wv : Wg;
    size_t i = ((size_t)blockIdx.x * 256 + threadIdx.x) * 8;
    float4 v0 = *(const float4*)(W + i);
    float4 v1 = *(const float4*)(W + i + 4);
    __half2 h[4];
    h[0] = __floats2half2_rn(v0.x, v0.y);
    h[1] = __floats2half2_rn(v0.z, v0.w);
    h[2] = __floats2half2_rn(v1.x, v1.y);
    h[3] = __floats2half2_rn(v1.z, v1.w);
    *(uint4*)(g_wh + (size_t)y * DD * EE + i) = *(uint4*)h;
}

// ---------------------------------------------------------------------------
// Paired fp16 GEMM on mma.sync: ONE CTA computes the same (M,N) tile for TWO
// weight matrices and writes only the elementwise product:
//   z=0: qg = (x.Wq^T + bq) * sigmoid(x.Wg^T + bg)
//   z=1: kv = (x.Wk^T + bk) * (x.Wv^T + bv)
// CTA M=128 x N=64 (x2 outputs), BK=64, 3-stage cp.async, warps 2(m) x 4(n).
// ---------------------------------------------------------------------------
__global__ __launch_bounds__(256, 2) void gemm_pair(
    const float* __restrict__ bq, const float* __restrict__ bk,
    const float* __restrict__ bv, const float* __restrict__ bg)
{
    extern __shared__ char smem[];
    const uint32_t sb = smem_u32(smem);
    const int tid = threadIdx.x;
    const int wid = tid >> 5, lane = tid & 31;
    const int wm = wid >> 2, wn = wid & 3;           // warps 2(m) x 4(n)
    const int z = blockIdx.z;
    const size_t m0 = (size_t)blockIdx.y * Bb_M;
    const size_t n0 = (size_t)blockIdx.x * Bb_N;

    // weight indices in g_wh: 0=q, 1=k, 2=v, 3=g
    const int w0i = z ? 1 : 0;
    const int w1i = z ? 2 : 3;
    const float* bias0 = z ? bk : bq;
    const float* bias1 = z ? bv : bg;
    float* outp = z ? g_kv : g_qg;

    const char* Ag  = (const char*)g_xh + m0 * (DD * 2);
    const char* B0g = (const char*)(g_wh + (size_t)w0i * DD * EE) + n0 * (DD * 2);
    const char* B1g = (const char*)(g_wh + (size_t)w1i * DD * EE) + n0 * (DD * 2);

    const int lrow = tid >> 3;        // 0..31
    const int lch  = tid & 7;         // 0..7

    auto load_stage = [&](int buf, int kb) {
        const uint32_t sbase = sb + buf * STAGE_BYTES;
        const size_t kbyte = (size_t)kb * 128;
        #pragma unroll
        for (int j = 0; j < 4; j++) {          // A: 128 rows
            int row = lrow + j * 32;
            size_t goff = (size_t)row * (DD * 2) + kbyte + lch * 16;
            cp_async16(sbase + A_OFF + swz((uint32_t)row, (uint32_t)lch), Ag + goff);
        }
        #pragma unroll
        for (int j = 0; j < 4; j++) {          // B: rows 0-63 = W0, 64-127 = W1
            int row = lrow + j * 32;
            const char* src = (row < 64)
                ? (B0g + (size_t)row * (DD * 2) + kbyte + lch * 16)
                : (B1g + (size_t)(row - 64) * (DD * 2) + kbyte + lch * 16);
            cp_async16(sbase + B_OFF + swz((uint32_t)row, (uint32_t)lch), src);
        }
    };

    float acc0[4][2][4], acc1[4][2][4];   // [mi][s][frag] for each output
    #pragma unroll
    for (int mi = 0; mi < 4; mi++)
        #pragma unroll
        for (int s = 0; s < 2; s++)
            #pragma unroll
            for (int e = 0; e < 4; e++) { acc0[mi][s][e] = 0.f; acc1[mi][s][e] = 0.f; }

    load_stage(0, 0); CP_COMMIT();
    load_stage(1, 1); CP_COMMIT();

    // ldmatrix lane->addr mapping
    const uint32_t arow = (uint32_t)(wm * 64) + (uint32_t)(lane & 15); // + mi*16
    const uint32_t ahib = (uint32_t)(lane >> 4);
    const uint32_t brow = (uint32_t)(wn * 16) + (uint32_t)(lane & 7) +
                          (uint32_t)((lane & 16) >> 1);                // 16-row group
    const uint32_t bhib = (uint32_t)((lane >> 3) & 1);

    for (int kb = 0; kb < KSTAGES; kb++) {
        if (kb + 1 < KSTAGES) { CP_WAIT1(); } else { CP_WAIT0(); }
        __syncthreads();
        if (kb + 2 < KSTAGES) { load_stage((kb + 2) % NSTAGE, kb + 2); CP_COMMIT(); }

        const uint32_t sbase = sb + (kb % NSTAGE) * STAGE_BYTES;
        #pragma unroll
        for (int kk = 0; kk < 4; kk++) {
            uint32_t af[4][4];
            #pragma unroll
            for (int mi = 0; mi < 4; mi++) {
                uint32_t off = swz(arow + mi * 16, kk * 2 + ahib);
                ldsm4(af[mi], sbase + A_OFF + off);
            }
            uint32_t b0f[4], b1f[4];
            {
                uint32_t off0 = swz(brow, kk * 2 + bhib);
                uint32_t off1 = swz(brow + 64, kk * 2 + bhib);
                ldsm4(b0f, sbase + B_OFF + off0);
                ldsm4(b1f, sbase + B_OFF + off1);
            }
            #pragma unroll
            for (int mi = 0; mi < 4; mi++) {
                #pragma unroll
                for (int s = 0; s < 2; s++) {
                    mma16816h(acc0[mi][s], af[mi], b0f[s*2], b0f[s*2+1]);
                    mma16816h(acc1[mi][s], af[mi], b1f[s*2], b1f[s*2+1]);
                }
            }
        }
    }

    // Epilogue: p = acc0 + bias0 ; r = acc1 + bias1 (sigmoid for z==0);
    // write p*r as float2.
    const int crow = lane >> 2;          // 0..7
    const int ccol = (lane & 3) * 2;     // 0,2,4,6
    #pragma unroll
    for (int s = 0; s < 2; s++) {
        size_t n = n0 + wn * 16 + s * 8 + ccol;
        float p0b = __ldg(bias0 + n), p1b = __ldg(bias0 + n + 1);
        float r0b = __ldg(bias1 + n), r1b = __ldg(bias1 + n + 1);
        #pragma unroll
        for (int mi = 0; mi < 4; mi++) {
            size_t m = m0 + wm * 64 + mi * 16 + crow;
            float pA0 = acc0[mi][s][0] + p0b, pA1 = acc0[mi][s][1] + p1b;
            float pB0 = acc0[mi][s][2] + p0b, pB1 = acc0[mi][s][3] + p1b;
            float rA0 = acc1[mi][s][0] + r0b, rA1 = acc1[mi][s][1] + r1b;
            float rB0 = acc1[mi][s][2] + r0b, rB1 = acc1[mi][s][3] + r1b;
            if (z == 0) {
                rA0 = 1.f/(1.f+expf(-rA0)); rA1 = 1.f/(1.f+expf(-rA1));
                rB0 = 1.f/(1.f+expf(-rB0)); rB1 = 1.f/(1.f+expf(-rB1));
            }
            *(float2*)(outp + m * (size_t)EE + n) =
                make_float2(pA0 * rA0, pA1 * rA1);
            *(float2*)(outp + (m + 8) * (size_t)EE + n) =
                make_float2(pB0 * rB0, pB1 * rB1);
        }
    }
}

// ---------------------------------------------------------------------------
// Scan pass 1: per-chunk sums of kv
// ---------------------------------------------------------------------------
__global__ __launch_bounds__(256) void chunk_sums()
{
    const int e = blockIdx.x * 256 + threadIdx.x;
    const int c = blockIdx.y;
    const int b = blockIdx.z;
    size_t idx = ((size_t)(b * SS + c * LCHUNK)) * EE + e;
    float s = 0.f;
    #pragma unroll 8
    for (int i = 0; i < LCHUNK; i++) {
        s += g_kv[idx];
        idx += EE;
    }
    g_sums[((size_t)b * EE + e) * NCHUNK + c] = s;
}

// ---------------------------------------------------------------------------
// Scan pass 2: exclusive scan of chunk sums (in place)
// ---------------------------------------------------------------------------
__global__ __launch_bounds__(256) void scan_sums()
{
    const int t = blockIdx.x * 256 + threadIdx.x;
    float* p = g_sums + (size_t)t * NCHUNK;
    float v[NCHUNK];
    #pragma unroll
    for (int c = 0; c < NCHUNK; c++) v[c] = p[c];
    float run = 0.f;
    #pragma unroll
    for (int c = 0; c < NCHUNK; c++) { float t2 = v[c]; v[c] = run; run += t2; }
    #pragma unroll
    for (int c = 0; c < NCHUNK; c++) p[c] = v[c];
}

// ---------------------------------------------------------------------------
// Scan pass 3: local inclusive scan + qg * state
// ---------------------------------------------------------------------------
__global__ __launch_bounds__(256) void finalize(float* __restrict__ out)
{
    const int e = blockIdx.x * 256 + threadIdx.x;
    const int c = blockIdx.y;
    const int b = blockIdx.z;
    float run = g_sums[((size_t)b * EE + e) * NCHUNK + c];
    size_t idx = ((size_t)(b * SS + c * LCHUNK)) * EE + e;
    #pragma unroll 4
    for (int i = 0; i < LCHUNK; i++) {
        run += g_kv[idx];
        out[idx] = g_qg[idx] * run;
        idx += EE;
    }
}

// ---------------------------------------------------------------------------
// Launch
// ---------------------------------------------------------------------------
extern "C" void kernel_launch(void* const* d_in, const int* in_sizes, int n_in,
                              void* d_out, int out_size)
{
    const float* x  = (const float*)d_in[0];
    const float* Wq = (const float*)d_in[1];
    const float* bq = (const float*)d_in[2];
    const float* Wk = (const float*)d_in[3];
    const float* bk = (const float*)d_in[4];
    const float* Wv = (const float*)d_in[5];
    const float* bv = (const float*)d_in[6];
    const float* Wg = (const float*)d_in[7];
    const float* bg = (const float*)d_in[8];
    float* out = (float*)d_out;

    cudaFuncSetAttribute(gemm_pair,
        cudaFuncAttributeMaxDynamicSharedMemorySize, SMEM_TOTAL);

    conv_x_kernel<<<(MM * (size_t)DD / 8) / 256, 256>>>(x);
    conv_w_kernel<<<dim3((DD * (size_t)EE / 8) / 256, 4), 256>>>(Wq, Wk, Wv, Wg);

    gemm_pair<<<dim3(EE/Bb_N, MM/Bb_M, 2), 256, SMEM_TOTAL>>>(bq, bk, bv, bg);

    dim3 gridC(EE / 256, NCHUNK, BB);
    chunk_sums<<<gridC, 256>>>();
    scan_sums<<<(BB * EE) / 256, 256>>>();
    finalize<<<gridC, 256>>>(out);
}

// round 10
// speedup vs baseline: 3.3936x; 1.0383x over previous
#include <cuda_runtime.h>
#include <cuda_fp16.h>
#include <cstdint>
#include <math.h>

// ---------------------------------------------------------------------------
// Problem dims
// ---------------------------------------------------------------------------
#define BB 4
#define SS 4096
#define DD 2048
#define EE 2048
#define MM (BB*SS)         // 16384
#define NCHUNK 64
#define LCHUNK (SS/NCHUNK) // 64

// GEMM tiling: CTA covers M=128 x N=64, TWO outputs per CTA (paired weights).
// BK=64, warps 2(m) x 4(n), warp tile 64m x 16n per output.
#define Bb_M 128
#define Bb_N 64
#define Bb_K 64
#define KSTAGES (DD/Bb_K)  // 32

// Stage smem (bytes): A 128 rows x 128B, B 128 rows (64 per weight) x 128B
#define A_OFF 0
#define B_OFF 16384
#define STAGE_BYTES 32768
#define NSTAGE 3
#define SMEM_TOTAL (NSTAGE*STAGE_BYTES)   // 98304 -> 2 CTAs/SM

// ---------------------------------------------------------------------------
// Device scratch
// ---------------------------------------------------------------------------
__device__ __half g_xh[(size_t)MM * DD];          // 64 MB fp16 x
__device__ __half g_wh[(size_t)4 * DD * EE];      // 32 MB fp16 W (q,k,v,g)
__device__ float g_qg[(size_t)MM * EE];           // 128 MB  q * sigmoid(g)
__device__ float g_kv[(size_t)MM * EE];           // 128 MB  k * v
__device__ float g_sums[(size_t)BB * EE * NCHUNK];

// ---------------------------------------------------------------------------
// Helpers (sm_80-era instructions only — compile at compute_103 baseline)
// ---------------------------------------------------------------------------
__device__ __forceinline__ uint32_t smem_u32(const void* p) {
    uint32_t a;
    asm("{ .reg .u64 t; cvta.to.shared.u64 t, %1; cvt.u32.u64 %0, t; }"
        : "=r"(a) : "l"(p));
    return a;
}
__device__ __forceinline__ void cp_async16(uint32_t dst, const void* src) {
    asm volatile("cp.async.cg.shared.global [%0], [%1], 16;"
                 :: "r"(dst), "l"(src) : "memory");
}
#define CP_COMMIT() asm volatile("cp.async.commit_group;" ::: "memory")
#define CP_WAIT1()  asm volatile("cp.async.wait_group 1;" ::: "memory")
#define CP_WAIT0()  asm volatile("cp.async.wait_group 0;" ::: "memory")

__device__ __forceinline__ void ldsm4(uint32_t (&r)[4], uint32_t addr) {
    asm volatile("ldmatrix.sync.aligned.m8n8.x4.shared.b16 {%0,%1,%2,%3}, [%4];"
                 : "=r"(r[0]), "=r"(r[1]), "=r"(r[2]), "=r"(r[3]) : "r"(addr));
}
__device__ __forceinline__ void mma16816h(float (&c)[4], const uint32_t (&a)[4],
                                          uint32_t b0, uint32_t b1) {
    asm volatile("mma.sync.aligned.m16n8k16.row.col.f32.f16.f16.f32 "
                 "{%0,%1,%2,%3}, {%4,%5,%6,%7}, {%8,%9}, {%0,%1,%2,%3};"
                 : "+f"(c[0]), "+f"(c[1]), "+f"(c[2]), "+f"(c[3])
                 : "r"(a[0]), "r"(a[1]), "r"(a[2]), "r"(a[3]), "r"(b0), "r"(b1));
}
// SW128 swizzled byte offset inside a [row][128B] tile
__device__ __forceinline__ uint32_t swz(uint32_t row, uint32_t ch) {
    return row * 128u + (((ch ^ (row & 7u)) & 7u) << 4);
}

// ---------------------------------------------------------------------------
// fp32 -> fp16 conversions (8 elems/thread)
// ---------------------------------------------------------------------------
__global__ __launch_bounds__(256) void conv_x_kernel(const float* __restrict__ x)
{
    size_t i = ((size_t)blockIdx.x * 256 + threadIdx.x) * 8;
    float4 v0 = *(const float4*)(x + i);
    float4 v1 = *(const float4*)(x + i + 4);
    __half2 h[4];
    h[0] = __floats2half2_rn(v0.x, v0.y);
    h[1] = __floats2half2_rn(v0.z, v0.w);
    h[2] = __floats2half2_rn(v1.x, v1.y);
    h[3] = __floats2half2_rn(v1.z, v1.w);
    *(uint4*)(g_xh + i) = *(uint4*)h;
}

__global__ __launch_bounds__(256) void conv_w_kernel(
    const float* __restrict__ Wq, const float* __restrict__ Wk,
    const float* __restrict__ Wv, const float* __restrict__ Wg)
{
    int y = blockIdx.y;
    const float* W = (y == 0) ? Wq : (y == 1) ? Wk : (y == 2) ? Wv : Wg;
    size_t i = ((size_t)blockIdx.x * 256 + threadIdx.x) * 8;
    float4 v0 = *(const float4*)(W + i);
    float4 v1 = *(const float4*)(W + i + 4);
    __half2 h[4];
    h[0] = __floats2half2_rn(v0.x, v0.y);
    h[1] = __floats2half2_rn(v0.z, v0.w);
    h[2] = __floats2half2_rn(v1.x, v1.y);
    h[3] = __floats2half2_rn(v1.z, v1.w);
    *(uint4*)(g_wh + (size_t)y * DD * EE + i) = *(uint4*)h;
}

// ---------------------------------------------------------------------------
// Paired fp16 GEMM on mma.sync: ONE CTA computes the same (M,N) tile for TWO
// weight matrices and writes only the elementwise product:
//   z=0: qg = (x.Wq^T + bq) * sigmoid(x.Wg^T + bg)
//   z=1: kv = (x.Wk^T + bk) * (x.Wv^T + bv)   + fused per-chunk column sums
// CTA M=128 x N=64 (x2 outputs), BK=64, 3-stage cp.async, warps 2(m) x 4(n).
// For z=1, warp wm holds exactly one scan chunk (64 seq rows): reduce kv over
// rows in-register (shfl) and store chunk sums directly -> no chunk_sums pass.
// ---------------------------------------------------------------------------
__global__ __launch_bounds__(256, 2) void gemm_pair(
    const float* __restrict__ bq, const float* __restrict__ bk,
    const float* __restrict__ bv, const float* __restrict__ bg)
{
    extern __shared__ char smem[];
    const uint32_t sb = smem_u32(smem);
    const int tid = threadIdx.x;
    const int wid = tid >> 5, lane = tid & 31;
    const int wm = wid >> 2, wn = wid & 3;           // warps 2(m) x 4(n)
    const int z = blockIdx.z;
    const size_t m0 = (size_t)blockIdx.y * Bb_M;
    const size_t n0 = (size_t)blockIdx.x * Bb_N;

    // weight indices in g_wh: 0=q, 1=k, 2=v, 3=g
    const int w0i = z ? 1 : 0;
    const int w1i = z ? 2 : 3;
    const float* bias0 = z ? bk : bq;
    const float* bias1 = z ? bv : bg;
    float* outp = z ? g_kv : g_qg;

    const char* Ag  = (const char*)g_xh + m0 * (DD * 2);
    const char* B0g = (const char*)(g_wh + (size_t)w0i * DD * EE) + n0 * (DD * 2);
    const char* B1g = (const char*)(g_wh + (size_t)w1i * DD * EE) + n0 * (DD * 2);

    const int lrow = tid >> 3;        // 0..31
    const int lch  = tid & 7;         // 0..7

    auto load_stage = [&](int buf, int kb) {
        const uint32_t sbase = sb + buf * STAGE_BYTES;
        const size_t kbyte = (size_t)kb * 128;
        #pragma unroll
        for (int j = 0; j < 4; j++) {          // A: 128 rows
            int row = lrow + j * 32;
            size_t goff = (size_t)row * (DD * 2) + kbyte + lch * 16;
            cp_async16(sbase + A_OFF + swz((uint32_t)row, (uint32_t)lch), Ag + goff);
        }
        #pragma unroll
        for (int j = 0; j < 4; j++) {          // B: rows 0-63 = W0, 64-127 = W1
            int row = lrow + j * 32;
            const char* src = (row < 64)
                ? (B0g + (size_t)row * (DD * 2) + kbyte + lch * 16)
                : (B1g + (size_t)(row - 64) * (DD * 2) + kbyte + lch * 16);
            cp_async16(sbase + B_OFF + swz((uint32_t)row, (uint32_t)lch), src);
        }
    };

    float acc0[4][2][4], acc1[4][2][4];   // [mi][s][frag] for each output
    #pragma unroll
    for (int mi = 0; mi < 4; mi++)
        #pragma unroll
        for (int s = 0; s < 2; s++)
            #pragma unroll
            for (int e = 0; e < 4; e++) { acc0[mi][s][e] = 0.f; acc1[mi][s][e] = 0.f; }

    load_stage(0, 0); CP_COMMIT();
    load_stage(1, 1); CP_COMMIT();

    // ldmatrix lane->addr mapping
    const uint32_t arow = (uint32_t)(wm * 64) + (uint32_t)(lane & 15); // + mi*16
    const uint32_t ahib = (uint32_t)(lane >> 4);
    const uint32_t brow = (uint32_t)(wn * 16) + (uint32_t)(lane & 7) +
                          (uint32_t)((lane & 16) >> 1);                // 16-row group
    const uint32_t bhib = (uint32_t)((lane >> 3) & 1);

    for (int kb = 0; kb < KSTAGES; kb++) {
        if (kb + 1 < KSTAGES) { CP_WAIT1(); } else { CP_WAIT0(); }
        __syncthreads();
        if (kb + 2 < KSTAGES) { load_stage((kb + 2) % NSTAGE, kb + 2); CP_COMMIT(); }

        const uint32_t sbase = sb + (kb % NSTAGE) * STAGE_BYTES;
        #pragma unroll
        for (int kk = 0; kk < 4; kk++) {
            uint32_t af[4][4];
            #pragma unroll
            for (int mi = 0; mi < 4; mi++) {
                uint32_t off = swz(arow + mi * 16, kk * 2 + ahib);
                ldsm4(af[mi], sbase + A_OFF + off);
            }
            uint32_t b0f[4], b1f[4];
            {
                uint32_t off0 = swz(brow, kk * 2 + bhib);
                uint32_t off1 = swz(brow + 64, kk * 2 + bhib);
                ldsm4(b0f, sbase + B_OFF + off0);
                ldsm4(b1f, sbase + B_OFF + off1);
            }
            #pragma unroll
            for (int mi = 0; mi < 4; mi++) {
                #pragma unroll
                for (int s = 0; s < 2; s++) {
                    mma16816h(acc0[mi][s], af[mi], b0f[s*2], b0f[s*2+1]);
                    mma16816h(acc1[mi][s], af[mi], b1f[s*2], b1f[s*2+1]);
                }
            }
        }
    }

    // Epilogue: p = acc0 + bias0 ; r = acc1 + bias1 (sigmoid for z==0);
    // write p*r; for z==1 also accumulate per-chunk column sums.
    const int crow = lane >> 2;          // 0..7
    const int ccol = (lane & 3) * 2;     // 0,2,4,6
    float colsum[2][2] = {{0.f, 0.f}, {0.f, 0.f}};
    #pragma unroll
    for (int s = 0; s < 2; s++) {
        size_t n = n0 + wn * 16 + s * 8 + ccol;
        float p0b = __ldg(bias0 + n), p1b = __ldg(bias0 + n + 1);
        float r0b = __ldg(bias1 + n), r1b = __ldg(bias1 + n + 1);
        #pragma unroll
        for (int mi = 0; mi < 4; mi++) {
            size_t m = m0 + wm * 64 + mi * 16 + crow;
            float pA0 = acc0[mi][s][0] + p0b, pA1 = acc0[mi][s][1] + p1b;
            float pB0 = acc0[mi][s][2] + p0b, pB1 = acc0[mi][s][3] + p1b;
            float rA0 = acc1[mi][s][0] + r0b, rA1 = acc1[mi][s][1] + r1b;
            float rB0 = acc1[mi][s][2] + r0b, rB1 = acc1[mi][s][3] + r1b;
            if (z == 0) {
                rA0 = 1.f/(1.f+expf(-rA0)); rA1 = 1.f/(1.f+expf(-rA1));
                rB0 = 1.f/(1.f+expf(-rB0)); rB1 = 1.f/(1.f+expf(-rB1));
            }
            float kvA0 = pA0 * rA0, kvA1 = pA1 * rA1;
            float kvB0 = pB0 * rB0, kvB1 = pB1 * rB1;
            if (z == 1) {
                colsum[s][0] += kvA0 + kvB0;
                colsum[s][1] += kvA1 + kvB1;
            }
            *(float2*)(outp + m * (size_t)EE + n) = make_float2(kvA0, kvA1);
            *(float2*)(outp + (m + 8) * (size_t)EE + n) = make_float2(kvB0, kvB1);
        }
    }

    if (z == 1) {
        // reduce colsum over the 8 crow groups (lanes sharing lane&3)
        #pragma unroll
        for (int s = 0; s < 2; s++) {
            #pragma unroll
            for (int j = 0; j < 2; j++) {
                float v = colsum[s][j];
                v += __shfl_xor_sync(0xffffffffu, v, 4);
                v += __shfl_xor_sync(0xffffffffu, v, 8);
                v += __shfl_xor_sync(0xffffffffu, v, 16);
                colsum[s][j] = v;
            }
        }
        if (lane < 4) {
            const int b = (int)(m0 >> 12);                 // m0 / 4096
            const int c = (int)((m0 & 4095) >> 6) + wm;    // chunk in batch
            #pragma unroll
            for (int s = 0; s < 2; s++) {
                size_t e = n0 + wn * 16 + s * 8 + lane * 2;
                g_sums[((size_t)b * EE + e)     * NCHUNK + c] = colsum[s][0];
                g_sums[((size_t)b * EE + e + 1) * NCHUNK + c] = colsum[s][1];
            }
        }
    }
}

// ---------------------------------------------------------------------------
// Exclusive scan of chunk sums (in place): one warp per chain of 64,
// float2 per lane, shfl inclusive scan -> coalesced.
// ---------------------------------------------------------------------------
__global__ __launch_bounds__(256) void scan_sums()
{
    const int wid = threadIdx.x >> 5, lane = threadIdx.x & 31;
    const size_t chain = (size_t)blockIdx.x * 8 + wid;     // 0..8191
    float* p = g_sums + chain * NCHUNK;
    float2 vv = *(float2*)(p + lane * 2);
    float pairsum = vv.x + vv.y;
    float inc = pairsum;
    #pragma unroll
    for (int d = 1; d < 32; d <<= 1) {
        float t = __shfl_up_sync(0xffffffffu, inc, d);
        if (lane >= d) inc += t;
    }
    float excl = inc - pairsum;
    *(float2*)(p + lane * 2) = make_float2(excl, excl + vv.x);
}

// ---------------------------------------------------------------------------
// Finalize: local inclusive scan + qg * state
// ---------------------------------------------------------------------------
__global__ __launch_bounds__(256) void finalize(float* __restrict__ out)
{
    const int e = blockIdx.x * 256 + threadIdx.x;
    const int c = blockIdx.y;
    const int b = blockIdx.z;
    float run = g_sums[((size_t)b * EE + e) * NCHUNK + c];
    size_t idx = ((size_t)(b * SS + c * LCHUNK)) * EE + e;
    #pragma unroll 4
    for (int i = 0; i < LCHUNK; i++) {
        run += g_kv[idx];
        out[idx] = g_qg[idx] * run;
        idx += EE;
    }
}

// ---------------------------------------------------------------------------
// Launch
// ---------------------------------------------------------------------------
extern "C" void kernel_launch(void* const* d_in, const int* in_sizes, int n_in,
                              void* d_out, int out_size)
{
    const float* x  = (const float*)d_in[0];
    const float* Wq = (const float*)d_in[1];
    const float* bq = (const float*)d_in[2];
    const float* Wk = (const float*)d_in[3];
    const float* bk = (const float*)d_in[4];
    const float* Wv = (const float*)d_in[5];
    const float* bv = (const float*)d_in[6];
    const float* Wg = (const float*)d_in[7];
    const float* bg = (const float*)d_in[8];
    float* out = (float*)d_out;

    cudaFuncSetAttribute(gemm_pair,
        cudaFuncAttributeMaxDynamicSharedMemorySize, SMEM_TOTAL);

    conv_x_kernel<<<(MM * (size_t)DD / 8) / 256, 256>>>(x);
    conv_w_kernel<<<dim3((DD * (size_t)EE / 8) / 256, 4), 256>>>(Wq, Wk, Wv, Wg);

    gemm_pair<<<dim3(EE/Bb_N, MM/Bb_M, 2), 256, SMEM_TOTAL>>>(bq, bk, bv, bg);

    scan_sums<<<(BB * EE) / 8, 256>>>();

    dim3 gridF(EE / 256, NCHUNK, BB);
    finalize<<<gridF, 256>>>(out);
}

// round 11
// speedup vs baseline: 3.4497x; 1.0165x over previous
#include <cuda_runtime.h>
#include <cuda_fp16.h>
#include <cstdint>
#include <math.h>

// ---------------------------------------------------------------------------
// Problem dims
// ---------------------------------------------------------------------------
#define BB 4
#define SS 4096
#define DD 2048
#define EE 2048
#define MM (BB*SS)         // 16384
#define NCHUNK 64
#define LCHUNK (SS/NCHUNK) // 64

// GEMM tiling: CTA covers M=128 x N=64, TWO outputs per CTA (paired weights).
// BK=64, warps 2(m) x 4(n), warp tile 64m x 16n per output.
#define Bb_M 128
#define Bb_N 64
#define Bb_K 64
#define KSTAGES (DD/Bb_K)  // 32

// Stage smem (bytes): A 128 rows x 128B, B 128 rows (64 per weight) x 128B
#define A_OFF 0
#define B_OFF 16384
#define STAGE_BYTES 32768
#define NSTAGE 3
#define SMEM_TOTAL (NSTAGE*STAGE_BYTES)   // 98304 -> 2 CTAs/SM

// ---------------------------------------------------------------------------
// Device scratch
// ---------------------------------------------------------------------------
__device__ __half g_xh[(size_t)MM * DD];          // 64 MB fp16 x
__device__ __half g_wh[(size_t)4 * DD * EE];      // 32 MB fp16 W (q,k,v,g)
__device__ __half g_qg[(size_t)MM * EE];          // 64 MB  q * sigmoid(g)  (fp16)
__device__ __half g_kv[(size_t)MM * EE];          // 64 MB  k * v           (fp16)
__device__ float g_sums[(size_t)BB * EE * NCHUNK];

// ---------------------------------------------------------------------------
// Helpers (sm_80-era instructions only — compile at compute_103 baseline)
// ---------------------------------------------------------------------------
__device__ __forceinline__ uint32_t smem_u32(const void* p) {
    uint32_t a;
    asm("{ .reg .u64 t; cvta.to.shared.u64 t, %1; cvt.u32.u64 %0, t; }"
        : "=r"(a) : "l"(p));
    return a;
}
__device__ __forceinline__ void cp_async16(uint32_t dst, const void* src) {
    asm volatile("cp.async.cg.shared.global [%0], [%1], 16;"
                 :: "r"(dst), "l"(src) : "memory");
}
#define CP_COMMIT() asm volatile("cp.async.commit_group;" ::: "memory")
#define CP_WAIT1()  asm volatile("cp.async.wait_group 1;" ::: "memory")
#define CP_WAIT0()  asm volatile("cp.async.wait_group 0;" ::: "memory")

__device__ __forceinline__ void ldsm4(uint32_t (&r)[4], uint32_t addr) {
    asm volatile("ldmatrix.sync.aligned.m8n8.x4.shared.b16 {%0,%1,%2,%3}, [%4];"
                 : "=r"(r[0]), "=r"(r[1]), "=r"(r[2]), "=r"(r[3]) : "r"(addr));
}
__device__ __forceinline__ void mma16816h(float (&c)[4], const uint32_t (&a)[4],
                                          uint32_t b0, uint32_t b1) {
    asm volatile("mma.sync.aligned.m16n8k16.row.col.f32.f16.f16.f32 "
                 "{%0,%1,%2,%3}, {%4,%5,%6,%7}, {%8,%9}, {%0,%1,%2,%3};"
                 : "+f"(c[0]), "+f"(c[1]), "+f"(c[2]), "+f"(c[3])
                 : "r"(a[0]), "r"(a[1]), "r"(a[2]), "r"(a[3]), "r"(b0), "r"(b1));
}
// SW128 swizzled byte offset inside a [row][128B] tile
__device__ __forceinline__ uint32_t swz(uint32_t row, uint32_t ch) {
    return row * 128u + (((ch ^ (row & 7u)) & 7u) << 4);
}

// ---------------------------------------------------------------------------
// fp32 -> fp16 conversions (8 elems/thread)
// ---------------------------------------------------------------------------
__global__ __launch_bounds__(256) void conv_x_kernel(const float* __restrict__ x)
{
    size_t i = ((size_t)blockIdx.x * 256 + threadIdx.x) * 8;
    float4 v0 = *(const float4*)(x + i);
    float4 v1 = *(const float4*)(x + i + 4);
    __half2 h[4];
    h[0] = __floats2half2_rn(v0.x, v0.y);
    h[1] = __floats2half2_rn(v0.z, v0.w);
    h[2] = __floats2half2_rn(v1.x, v1.y);
    h[3] = __floats2half2_rn(v1.z, v1.w);
    *(uint4*)(g_xh + i) = *(uint4*)h;
}

__global__ __launch_bounds__(256) void conv_w_kernel(
    const float* __restrict__ Wq, const float* __restrict__ Wk,
    const float* __restrict__ Wv, const float* __restrict__ Wg)
{
    int y = blockIdx.y;
    const float* W = (y == 0) ? Wq : (y == 1) ? Wk : (y == 2) ? Wv : Wg;
    size_t i = ((size_t)blockIdx.x * 256 + threadIdx.x) * 8;
    float4 v0 = *(const float4*)(W + i);
    float4 v1 = *(const float4*)(W + i + 4);
    __half2 h[4];
    h[0] = __floats2half2_rn(v0.x, v0.y);
    h[1] = __floats2half2_rn(v0.z, v0.w);
    h[2] = __floats2half2_rn(v1.x, v1.y);
    h[3] = __floats2half2_rn(v1.z, v1.w);
    *(uint4*)(g_wh + (size_t)y * DD * EE + i) = *(uint4*)h;
}

// ---------------------------------------------------------------------------
// Paired fp16 GEMM on mma.sync: ONE CTA computes the same (M,N) tile for TWO
// weight matrices and writes only the elementwise product (as fp16):
//   z=0: qg = (x.Wq^T + bq) * sigmoid(x.Wg^T + bg)
//   z=1: kv = (x.Wk^T + bk) * (x.Wv^T + bv)   + fused per-chunk column sums
// CTA M=128 x N=64 (x2 outputs), BK=64, 3-stage cp.async, warps 2(m) x 4(n).
// For z=1, warp wm holds exactly one scan chunk (64 seq rows): reduce kv over
// rows in-register (shfl, fp32 pre-rounding) and store chunk sums directly.
// ---------------------------------------------------------------------------
__global__ __launch_bounds__(256, 2) void gemm_pair(
    const float* __restrict__ bq, const float* __restrict__ bk,
    const float* __restrict__ bv, const float* __restrict__ bg)
{
    extern __shared__ char smem[];
    const uint32_t sb = smem_u32(smem);
    const int tid = threadIdx.x;
    const int wid = tid >> 5, lane = tid & 31;
    const int wm = wid >> 2, wn = wid & 3;           // warps 2(m) x 4(n)
    const int z = blockIdx.z;
    const size_t m0 = (size_t)blockIdx.y * Bb_M;
    const size_t n0 = (size_t)blockIdx.x * Bb_N;

    // weight indices in g_wh: 0=q, 1=k, 2=v, 3=g
    const int w0i = z ? 1 : 0;
    const int w1i = z ? 2 : 3;
    const float* bias0 = z ? bk : bq;
    const float* bias1 = z ? bv : bg;
    __half* outp = z ? g_kv : g_qg;

    const char* Ag  = (const char*)g_xh + m0 * (DD * 2);
    const char* B0g = (const char*)(g_wh + (size_t)w0i * DD * EE) + n0 * (DD * 2);
    const char* B1g = (const char*)(g_wh + (size_t)w1i * DD * EE) + n0 * (DD * 2);

    const int lrow = tid >> 3;        // 0..31
    const int lch  = tid & 7;         // 0..7

    auto load_stage = [&](int buf, int kb) {
        const uint32_t sbase = sb + buf * STAGE_BYTES;
        const size_t kbyte = (size_t)kb * 128;
        #pragma unroll
        for (int j = 0; j < 4; j++) {          // A: 128 rows
            int row = lrow + j * 32;
            size_t goff = (size_t)row * (DD * 2) + kbyte + lch * 16;
            cp_async16(sbase + A_OFF + swz((uint32_t)row, (uint32_t)lch), Ag + goff);
        }
        #pragma unroll
        for (int j = 0; j < 4; j++) {          // B: rows 0-63 = W0, 64-127 = W1
            int row = lrow + j * 32;
            const char* src = (row < 64)
                ? (B0g + (size_t)row * (DD * 2) + kbyte + lch * 16)
                : (B1g + (size_t)(row - 64) * (DD * 2) + kbyte + lch * 16);
            cp_async16(sbase + B_OFF + swz((uint32_t)row, (uint32_t)lch), src);
        }
    };

    float acc0[4][2][4], acc1[4][2][4];   // [mi][s][frag] for each output
    #pragma unroll
    for (int mi = 0; mi < 4; mi++)
        #pragma unroll
        for (int s = 0; s < 2; s++)
            #pragma unroll
            for (int e = 0; e < 4; e++) { acc0[mi][s][e] = 0.f; acc1[mi][s][e] = 0.f; }

    load_stage(0, 0); CP_COMMIT();
    load_stage(1, 1); CP_COMMIT();

    // ldmatrix lane->addr mapping
    const uint32_t arow = (uint32_t)(wm * 64) + (uint32_t)(lane & 15); // + mi*16
    const uint32_t ahib = (uint32_t)(lane >> 4);
    const uint32_t brow = (uint32_t)(wn * 16) + (uint32_t)(lane & 7) +
                          (uint32_t)((lane & 16) >> 1);                // 16-row group
    const uint32_t bhib = (uint32_t)((lane >> 3) & 1);

    for (int kb = 0; kb < KSTAGES; kb++) {
        if (kb + 1 < KSTAGES) { CP_WAIT1(); } else { CP_WAIT0(); }
        __syncthreads();
        if (kb + 2 < KSTAGES) { load_stage((kb + 2) % NSTAGE, kb + 2); CP_COMMIT(); }

        const uint32_t sbase = sb + (kb % NSTAGE) * STAGE_BYTES;
        #pragma unroll
        for (int kk = 0; kk < 4; kk++) {
            uint32_t af[4][4];
            #pragma unroll
            for (int mi = 0; mi < 4; mi++) {
                uint32_t off = swz(arow + mi * 16, kk * 2 + ahib);
                ldsm4(af[mi], sbase + A_OFF + off);
            }
            uint32_t b0f[4], b1f[4];
            {
                uint32_t off0 = swz(brow, kk * 2 + bhib);
                uint32_t off1 = swz(brow + 64, kk * 2 + bhib);
                ldsm4(b0f, sbase + B_OFF + off0);
                ldsm4(b1f, sbase + B_OFF + off1);
            }
            #pragma unroll
            for (int mi = 0; mi < 4; mi++) {
                #pragma unroll
                for (int s = 0; s < 2; s++) {
                    mma16816h(acc0[mi][s], af[mi], b0f[s*2], b0f[s*2+1]);
                    mma16816h(acc1[mi][s], af[mi], b1f[s*2], b1f[s*2+1]);
                }
            }
        }
    }

    // Epilogue: p = acc0 + bias0 ; r = acc1 + bias1 (sigmoid for z==0);
    // write p*r as half2; for z==1 also accumulate per-chunk column sums (fp32).
    const int crow = lane >> 2;          // 0..7
    const int ccol = (lane & 3) * 2;     // 0,2,4,6
    float colsum[2][2] = {{0.f, 0.f}, {0.f, 0.f}};
    #pragma unroll
    for (int s = 0; s < 2; s++) {
        size_t n = n0 + wn * 16 + s * 8 + ccol;
        float p0b = __ldg(bias0 + n), p1b = __ldg(bias0 + n + 1);
        float r0b = __ldg(bias1 + n), r1b = __ldg(bias1 + n + 1);
        #pragma unroll
        for (int mi = 0; mi < 4; mi++) {
            size_t m = m0 + wm * 64 + mi * 16 + crow;
            float pA0 = acc0[mi][s][0] + p0b, pA1 = acc0[mi][s][1] + p1b;
            float pB0 = acc0[mi][s][2] + p0b, pB1 = acc0[mi][s][3] + p1b;
            float rA0 = acc1[mi][s][0] + r0b, rA1 = acc1[mi][s][1] + r1b;
            float rB0 = acc1[mi][s][2] + r0b, rB1 = acc1[mi][s][3] + r1b;
            if (z == 0) {
                rA0 = 1.f/(1.f+expf(-rA0)); rA1 = 1.f/(1.f+expf(-rA1));
                rB0 = 1.f/(1.f+expf(-rB0)); rB1 = 1.f/(1.f+expf(-rB1));
            }
            float kvA0 = pA0 * rA0, kvA1 = pA1 * rA1;
            float kvB0 = pB0 * rB0, kvB1 = pB1 * rB1;
            if (z == 1) {
                colsum[s][0] += kvA0 + kvB0;
                colsum[s][1] += kvA1 + kvB1;
            }
            *(__half2*)(outp + m * (size_t)EE + n) = __floats2half2_rn(kvA0, kvA1);
            *(__half2*)(outp + (m + 8) * (size_t)EE + n) = __floats2half2_rn(kvB0, kvB1);
        }
    }

    if (z == 1) {
        // reduce colsum over the 8 crow groups (lanes sharing lane&3)
        #pragma unroll
        for (int s = 0; s < 2; s++) {
            #pragma unroll
            for (int j = 0; j < 2; j++) {
                float v = colsum[s][j];
                v += __shfl_xor_sync(0xffffffffu, v, 4);
                v += __shfl_xor_sync(0xffffffffu, v, 8);
                v += __shfl_xor_sync(0xffffffffu, v, 16);
                colsum[s][j] = v;
            }
        }
        if (lane < 4) {
            const int b = (int)(m0 >> 12);                 // m0 / 4096
            const int c = (int)((m0 & 4095) >> 6) + wm;    // chunk in batch
            #pragma unroll
            for (int s = 0; s < 2; s++) {
                size_t e = n0 + wn * 16 + s * 8 + lane * 2;
                g_sums[((size_t)b * EE + e)     * NCHUNK + c] = colsum[s][0];
                g_sums[((size_t)b * EE + e + 1) * NCHUNK + c] = colsum[s][1];
            }
        }
    }
}

// ---------------------------------------------------------------------------
// Exclusive scan of chunk sums (in place): one warp per chain of 64,
// float2 per lane, shfl inclusive scan -> coalesced.
// ---------------------------------------------------------------------------
__global__ __launch_bounds__(256) void scan_sums()
{
    const int wid = threadIdx.x >> 5, lane = threadIdx.x & 31;
    const size_t chain = (size_t)blockIdx.x * 8 + wid;     // 0..8191
    float* p = g_sums + chain * NCHUNK;
    float2 vv = *(float2*)(p + lane * 2);
    float pairsum = vv.x + vv.y;
    float inc = pairsum;
    #pragma unroll
    for (int d = 1; d < 32; d <<= 1) {
        float t = __shfl_up_sync(0xffffffffu, inc, d);
        if (lane >= d) inc += t;
    }
    float excl = inc - pairsum;
    *(float2*)(p + lane * 2) = make_float2(excl, excl + vv.x);
}

// ---------------------------------------------------------------------------
// Finalize: local inclusive scan + qg * state.  Two columns per thread
// (half2 loads of qg/kv, float2 stores of out).
// ---------------------------------------------------------------------------
__global__ __launch_bounds__(256) void finalize(float* __restrict__ out)
{
    const int e2 = blockIdx.x * 256 + threadIdx.x;   // column pair id, 0..1023
    const int e = e2 * 2;
    const int c = blockIdx.y;
    const int b = blockIdx.z;
    float run0 = g_sums[((size_t)b * EE + e)     * NCHUNK + c];
    float run1 = g_sums[((size_t)b * EE + e + 1) * NCHUNK + c];
    size_t idx = ((size_t)(b * SS + c * LCHUNK)) * EE + e;
    #pragma unroll 4
    for (int i = 0; i < LCHUNK; i++) {
        float2 kv = __half22float2(*(const __half2*)(g_kv + idx));
        float2 qg = __half22float2(*(const __half2*)(g_qg + idx));
        run0 += kv.x;
        run1 += kv.y;
        *(float2*)(out + idx) = make_float2(qg.x * run0, qg.y * run1);
        idx += EE;
    }
}

// ---------------------------------------------------------------------------
// Launch
// ---------------------------------------------------------------------------
extern "C" void kernel_launch(void* const* d_in, const int* in_sizes, int n_in,
                              void* d_out, int out_size)
{
    const float* x  = (const float*)d_in[0];
    const float* Wq = (const float*)d_in[1];
    const float* bq = (const float*)d_in[2];
    const float* Wk = (const float*)d_in[3];
    const float* bk = (const float*)d_in[4];
    const float* Wv = (const float*)d_in[5];
    const float* bv = (const float*)d_in[6];
    const float* Wg = (const float*)d_in[7];
    const float* bg = (const float*)d_in[8];
    float* out = (float*)d_out;

    cudaFuncSetAttribute(gemm_pair,
        cudaFuncAttributeMaxDynamicSharedMemorySize, SMEM_TOTAL);

    conv_x_kernel<<<(MM * (size_t)DD / 8) / 256, 256>>>(x);
    conv_w_kernel<<<dim3((DD * (size_t)EE / 8) / 256, 4), 256>>>(Wq, Wk, Wv, Wg);

    gemm_pair<<<dim3(EE/Bb_N, MM/Bb_M, 2), 256, SMEM_TOTAL>>>(bq, bk, bv, bg);

    scan_sums<<<(BB * EE) / 8, 256>>>();

    dim3 gridF(EE / 512, NCHUNK, BB);
    finalize<<<gridF, 256>>>(out);
}